// round 1
// baseline (speedup 1.0000x reference)
#include <cuda_runtime.h>
#include <cstdint>

// ---------------------------------------------------------------------------
// HierarchUpdateMlp — tf32 mma.sync implementation
//   L1:  out1[:,g] = relu(gather_g(update) @ W1g^T + b1g)   g=0..6
//   L2:  out2[:,g] = relu(gather_g(out1)   @ W2g^T + b2g)   g=0..5
//   L3:  out       = relu(out2 @ Wf^T + bf)
// Weights in [out,in] row-major are already the n-major B layout we need.
// ---------------------------------------------------------------------------

#define NROWS_MAX 50176   // 392 tiles of 128 (N = 50000)

__device__ __align__(16) float g_W1_0[128 * 1280];
__device__ __align__(16) float g_W1[6 * 128 * 512];
__device__ __align__(16) float g_W2[6 * 128 * 256];
__device__ __align__(16) float g_Wf[256 * 768];
__device__ __align__(16) float g_out1[(size_t)NROWS_MAX * 896];
__device__ __align__(16) float g_out2[(size_t)NROWS_MAX * 768];

__constant__ int c_jA[7] = {0, 5, 7, 8, 11, 13, 14};
__constant__ int c_jB[7] = {0, 6, 9, 10, 12, 15, 16};
__constant__ int c_pA[6] = {0, 1, 1, 1, 4, 4};
__constant__ int c_pB[6] = {1, 2, 3, 4, 5, 6};

__device__ __forceinline__ float tf32_round(float x) {
    unsigned u;
    asm("cvt.rna.tf32.f32 %0, %1;" : "=r"(u) : "f"(x));
    return __uint_as_float(u);
}

__device__ __forceinline__ unsigned smem_u32(const void* p) {
    return (unsigned)__cvta_generic_to_shared(p);
}

__device__ __forceinline__ void ldsm4(unsigned addr, unsigned& r0, unsigned& r1,
                                      unsigned& r2, unsigned& r3) {
    asm volatile("ldmatrix.sync.aligned.m8n8.x4.shared.b16 {%0,%1,%2,%3}, [%4];"
                 : "=r"(r0), "=r"(r1), "=r"(r2), "=r"(r3)
                 : "r"(addr));
}

__device__ __forceinline__ void mma_tf32(float* c, const unsigned* a, const unsigned* b) {
    asm volatile(
        "mma.sync.aligned.m16n8k8.row.col.f32.tf32.tf32.f32 "
        "{%0,%1,%2,%3}, {%4,%5,%6,%7}, {%8,%9}, {%0,%1,%2,%3};"
        : "+f"(c[0]), "+f"(c[1]), "+f"(c[2]), "+f"(c[3])
        : "r"(a[0]), "r"(a[1]), "r"(a[2]), "r"(a[3]), "r"(b[0]), "r"(b[1]));
}

// Generic 128(M) x 128(N) tile GEMM. A gathered from up to 2 contiguous blocks:
//   col(k) = (k < blk) ? offA0 + k : offA1 + (k - blk)
// B is n-major [128][K] (weight row-major [out][in]). K multiple of 32.
template <bool ROUND_OUT>
__device__ __forceinline__ void gemm_core(
    const float* __restrict__ A, int lda, int offA0, int offA1, int blk,
    const float* __restrict__ B, int ldb,
    const float* __restrict__ bias,
    float* __restrict__ C, int ldc,
    int K, int nrows)
{
    extern __shared__ float sm[];   // [As0 | As1 | Bs0 | Bs1], each 128x32 floats
    const int tid   = threadIdx.x;
    const int lane  = tid & 31;
    const int wid   = tid >> 5;
    const int warpM = wid & 3;      // 4 warps over M (32 rows each)
    const int warpN = wid >> 2;     // 2 warps over N (64 cols each)
    const int tile  = blockIdx.x * 128;

    float acc[2][8][4];
#pragma unroll
    for (int i = 0; i < 2; i++)
#pragma unroll
        for (int j = 0; j < 8; j++)
#pragma unroll
            for (int q = 0; q < 4; q++) acc[i][j][q] = 0.f;

    const int KT = K >> 5;

    // lane decomposition for ldmatrix address generation
    const int aRowIn = (lane & 7) + ((lane >> 3) & 1) * 8;
    const int aHi    = (lane >> 4) & 1;
    const int bRowIn = (lane & 7) + ((lane >> 4) & 1) * 8;
    const int bHi    = (lane >> 3) & 1;

    auto load_stage = [&](int kt, int buf) {
        float* As = sm + buf * 4096;
        float* Bs = sm + 8192 + buf * 4096;
#pragma unroll
        for (int i = 0; i < 4; ++i) {
            int idx = tid + i * 256;
            int r   = idx >> 3;          // 0..127
            int cc  = idx & 7;           // 16B chunk within 128B row
            int row = tile + r;
            if (row >= nrows) row = nrows - 1;   // clamp (stores are guarded)
            int kg  = (kt << 5) + cc * 4;
            int col = (kg < blk) ? (offA0 + kg) : (offA1 + (kg - blk));
            const float* srcA = A + (long)row * lda + col;
            unsigned dA = smem_u32(As + r * 32 + 4 * (cc ^ (r & 7)));
            asm volatile("cp.async.cg.shared.global [%0], [%1], 16;" ::"r"(dA), "l"(srcA));
            const float* srcB = B + (long)r * ldb + (kt << 5) + cc * 4;
            unsigned dB = smem_u32(Bs + r * 32 + 4 * (cc ^ (r & 7)));
            asm volatile("cp.async.cg.shared.global [%0], [%1], 16;" ::"r"(dB), "l"(srcB));
        }
        asm volatile("cp.async.commit_group;");
    };

    auto compute_stage = [&](int buf) {
        const float* As = sm + buf * 4096;
        const float* Bs = sm + 8192 + buf * 4096;
#pragma unroll
        for (int k8 = 0; k8 < 4; ++k8) {
            unsigned a[2][4];
#pragma unroll
            for (int mf = 0; mf < 2; ++mf) {
                int row   = warpM * 32 + mf * 16 + aRowIn;
                int chunk = ((k8 << 1) + aHi) ^ (row & 7);
                ldsm4(smem_u32(As + row * 32 + 4 * chunk),
                      a[mf][0], a[mf][1], a[mf][2], a[mf][3]);
            }
            unsigned b[8][2];
#pragma unroll
            for (int nq = 0; nq < 4; ++nq) {
                int nrow  = warpN * 64 + nq * 16 + bRowIn;
                int chunk = ((k8 << 1) + bHi) ^ (nrow & 7);
                unsigned r0, r1, r2, r3;
                ldsm4(smem_u32(Bs + nrow * 32 + 4 * chunk), r0, r1, r2, r3);
                b[nq * 2][0]     = r0;
                b[nq * 2][1]     = r1;
                b[nq * 2 + 1][0] = r2;
                b[nq * 2 + 1][1] = r3;
            }
#pragma unroll
            for (int mf = 0; mf < 2; ++mf)
#pragma unroll
                for (int nf = 0; nf < 8; ++nf)
                    mma_tf32(acc[mf][nf], a[mf], b[nf]);
        }
    };

    load_stage(0, 0);
    for (int kt = 0; kt < KT; ++kt) {
        int buf = kt & 1;
        if (kt + 1 < KT) {
            load_stage(kt + 1, buf ^ 1);
            asm volatile("cp.async.wait_group 1;" ::: "memory");
        } else {
            asm volatile("cp.async.wait_group 0;" ::: "memory");
        }
        __syncthreads();
        compute_stage(buf);
        __syncthreads();
    }

    // Epilogue: bias + relu (+ tf32 rounding so the next layer's operand is exact)
    const int rbase = tile + warpM * 32 + (lane >> 2);
#pragma unroll
    for (int mf = 0; mf < 2; ++mf) {
        int r0 = rbase + mf * 16;
#pragma unroll
        for (int nf = 0; nf < 8; ++nf) {
            int col  = warpN * 64 + nf * 8 + (lane & 3) * 2;
            float b0 = __ldg(bias + col);
            float b1 = __ldg(bias + col + 1);
            float v0 = fmaxf(acc[mf][nf][0] + b0, 0.f);
            float v1 = fmaxf(acc[mf][nf][1] + b1, 0.f);
            float v2 = fmaxf(acc[mf][nf][2] + b0, 0.f);
            float v3 = fmaxf(acc[mf][nf][3] + b1, 0.f);
            if (ROUND_OUT) {
                v0 = tf32_round(v0); v1 = tf32_round(v1);
                v2 = tf32_round(v2); v3 = tf32_round(v3);
            }
            if (r0 < nrows)
                *reinterpret_cast<float2*>(C + (long)r0 * ldc + col) = make_float2(v0, v1);
            if (r0 + 8 < nrows)
                *reinterpret_cast<float2*>(C + (long)(r0 + 8) * ldc + col) = make_float2(v2, v3);
        }
    }
}

// ---------------- kernels ----------------

__global__ void prep_kernel(const float* __restrict__ w10, const float* __restrict__ w1,
                            const float* __restrict__ w2, const float* __restrict__ wf) {
    int i      = blockIdx.x * blockDim.x + threadIdx.x;
    int stride = gridDim.x * blockDim.x;
    for (int j = i; j < 128 * 1280; j += stride) g_W1_0[j] = tf32_round(w10[j]);
    for (int j = i; j < 6 * 128 * 512; j += stride) g_W1[j] = tf32_round(w1[j]);
    for (int j = i; j < 6 * 128 * 256; j += stride) g_W2[j] = tf32_round(w2[j]);
    for (int j = i; j < 256 * 768; j += stride) g_Wf[j] = tf32_round(wf[j]);
}

__global__ void __launch_bounds__(256, 2)
l1_kernel(const float* __restrict__ update, const float* __restrict__ b1_0,
          const float* __restrict__ b1, int nrows) {
    int g = blockIdx.y;
    if (g == 0) {
        // joints 0..4 are contiguous columns 0..1279 of the 4352-wide row
        gemm_core<true>(update, 4352, 0, 0, 1 << 20,
                        g_W1_0, 1280, b1_0, g_out1, 896, 1280, nrows);
    } else {
        gemm_core<true>(update, 4352, c_jA[g] * 256, c_jB[g] * 256, 256,
                        g_W1 + (g - 1) * 128 * 512, 512, b1 + (g - 1) * 128,
                        g_out1 + g * 128, 896, 512, nrows);
    }
}

__global__ void __launch_bounds__(256, 2)
l2_kernel(const float* __restrict__ b2, int nrows) {
    int g = blockIdx.y;
    gemm_core<true>(g_out1, 896, c_pA[g] * 128, c_pB[g] * 128, 128,
                    g_W2 + g * 128 * 256, 256, b2 + g * 128,
                    g_out2 + g * 128, 768, 256, nrows);
}

__global__ void __launch_bounds__(256, 2)
l3_kernel(const float* __restrict__ bf, float* __restrict__ out, int nrows) {
    int y = blockIdx.y;   // output column half (0: cols 0..127, 1: 128..255)
    gemm_core<false>(g_out2, 768, 0, 0, 1 << 20,
                     g_Wf + y * 128 * 768, 768, bf + y * 128,
                     out + y * 128, 256, 768, nrows);
}

// ---------------- launch ----------------

extern "C" void kernel_launch(void* const* d_in, const int* in_sizes, int n_in,
                              void* d_out, int out_size) {
    const float* update = (const float*)d_in[0];
    const float* W1_0   = (const float*)d_in[1];
    const float* b1_0   = (const float*)d_in[2];
    const float* W1     = (const float*)d_in[3];
    const float* b1     = (const float*)d_in[4];
    const float* W2     = (const float*)d_in[5];
    const float* b2     = (const float*)d_in[6];
    const float* Wf     = (const float*)d_in[7];
    const float* bf     = (const float*)d_in[8];

    int N  = in_sizes[0] / (17 * 256);
    int MT = (N + 127) / 128;

    cudaFuncSetAttribute(l1_kernel, cudaFuncAttributeMaxDynamicSharedMemorySize, 65536);
    cudaFuncSetAttribute(l2_kernel, cudaFuncAttributeMaxDynamicSharedMemorySize, 65536);
    cudaFuncSetAttribute(l3_kernel, cudaFuncAttributeMaxDynamicSharedMemorySize, 65536);

    prep_kernel<<<232, 256>>>(W1_0, W1, W2, Wf);
    l1_kernel<<<dim3(MT, 7), 256, 65536>>>(update, b1_0, b1, N);
    l2_kernel<<<dim3(MT, 6), 256, 65536>>>(b2, N);
    l3_kernel<<<dim3(MT, 2), 256, 65536>>>(bf, (float*)d_out, N);
}